// round 15
// baseline (speedup 1.0000x reference)
#include <cuda_runtime.h>
#include <cuda_fp16.h>
#include <math.h>
#include <stdint.h>

#define N_INT 20000
#define N_B   800
#define HID   512
#define BROW  (4*N_INT)              // 80000
#define M_ROWS (BROW + N_B)          // 80800
#define M_TILES 1263                 // ceil(80800/64)
#define INT_TILES 1250               // 80000/64 : tiles below are pure interior
#define M_PAD (M_TILES*64)           // 80832 (pad rows stay zero forever)
#define ALPHA 0.01f
#define NCH 16                       // 512/32 k-chunks
#define LO_SCALE 2048.0f
#define INV_LO_SCALE 4.8828125e-4f   // 1/2048

// smem per stage: Ahi/Alo (64 x 40 halves) + Bhi/Blo (128 x 40 halves)
#define SROW 40
#define SM_AHI 0
#define SM_ALO 5120
#define SM_BHI 10240
#define SM_BLO 20480
#define STAGE  30720
#define NSTAGE 3
#define SMEM_DYN (NSTAGE*STAGE)      // 92160 B -> 2 CTAs/SM

// Activations as hi/lo fp16 pairs. lo parts stored PRE-SCALED by 2048 so the
// correction MMAs (fp16 accumulate) operate on O(1) values. Ping-pong A -> A2.
__device__ __half g_Ahi [(size_t)M_PAD * HID];
__device__ __half g_Alo [(size_t)M_PAD * HID];
__device__ __half g_A2hi[(size_t)M_PAD * HID];
__device__ __half g_A2lo[(size_t)M_PAD * HID];
__device__ __half g_W1hi[HID * HID];   // [n][k]
__device__ __half g_W1lo[HID * HID];
__device__ __half g_W2hi[HID * HID];
__device__ __half g_W2lo[HID * HID];
__device__ float  g_S [(size_t)N_INT * HID];
__device__ float  g_Yb[(size_t)N_B * HID];
__device__ float  g_partial_i[2500];
__device__ float  g_partial_b[100];

// ------------------------------- helpers -----------------------------------
static __device__ __forceinline__ uint32_t smem_u32(const void* p) {
    uint32_t a;
    asm("{ .reg .u64 t; cvta.to.shared.u64 t, %1; cvt.u32.u64 %0, t; }" : "=r"(a) : "l"(p));
    return a;
}
static __device__ __forceinline__ void cp16(uint32_t dst, const void* src) {
    asm volatile("cp.async.cg.shared.global [%0], [%1], 16;" :: "r"(dst), "l"(src));
}
static __device__ __forceinline__ void ldsm4(uint32_t* r, uint32_t addr) {
    asm volatile("ldmatrix.sync.aligned.m8n8.x4.shared.b16 {%0,%1,%2,%3}, [%4];"
                 : "=r"(r[0]), "=r"(r[1]), "=r"(r[2]), "=r"(r[3]) : "r"(addr));
}
static __device__ __forceinline__ void mma16816(float* d, const uint32_t* a, const uint32_t* b) {
    asm volatile(
        "mma.sync.aligned.m16n8k16.row.col.f32.f16.f16.f32 "
        "{%0,%1,%2,%3}, {%4,%5,%6,%7}, {%8,%9}, {%0,%1,%2,%3};"
        : "+f"(d[0]), "+f"(d[1]), "+f"(d[2]), "+f"(d[3])
        : "r"(a[0]), "r"(a[1]), "r"(a[2]), "r"(a[3]), "r"(b[0]), "r"(b[1]));
}
// fp16-accumulator MMA for the scaled correction terms.
static __device__ __forceinline__ void mma16816h(uint32_t* c, const uint32_t* a, const uint32_t* b) {
    asm volatile(
        "mma.sync.aligned.m16n8k16.row.col.f16.f16.f16.f16 "
        "{%0,%1}, {%2,%3,%4,%5}, {%6,%7}, {%0,%1};"
        : "+r"(c[0]), "+r"(c[1])
        : "r"(a[0]), "r"(a[1]), "r"(a[2]), "r"(a[3]), "r"(b[0]), "r"(b[1]));
}
// hi = rn(x); lo = rn((x - hi) * 2048)   (lo pre-scaled for fp16-acc MMAs)
static __device__ __forceinline__ void hsplit(float x, uint32_t& h, uint32_t& l) {
    __half hh = __float2half_rn(x);
    float  r  = (x - __half2float(hh)) * LO_SCALE;
    __half ll = __float2half_rn(r);
    h = __half_as_ushort(hh);
    l = __half_as_ushort(ll);
}
static __device__ __forceinline__ void load_frags(
    uint32_t cur, int ks, int wm, int wn, int aoff, int boff,
    uint32_t ahi[2][4], uint32_t alo[2][4], uint32_t bhi[2][4], uint32_t blo[2][4])
{
    #pragma unroll
    for (int mt = 0; mt < 2; mt++) {
        uint32_t base = cur + 2u * ((wm*32 + mt*16) * SROW + ks*16 + aoff);
        ldsm4(ahi[mt], base + SM_AHI);
        ldsm4(alo[mt], base + SM_ALO);
    }
    #pragma unroll
    for (int np = 0; np < 2; np++) {
        uint32_t base = cur + 2u * ((wn*32 + np*16) * SROW + ks*16 + boff);
        ldsm4(bhi[np], base + SM_BHI);
        ldsm4(blo[np], base + SM_BLO);
    }
}
// Main term (f32 acc) + two scaled correction terms (shared f16 acc C).
// Pass structure keeps same-C MMAs 8 apart (>= f16-acc latency at rate).
static __device__ __forceinline__ void do_mmas(
    float acc[2][4][4], uint32_t C[2][4][2],
    uint32_t ahi[2][4], uint32_t alo[2][4], uint32_t bhi[2][4], uint32_t blo[2][4])
{
    #pragma unroll
    for (int mt = 0; mt < 2; mt++)
        #pragma unroll
        for (int nt = 0; nt < 4; nt++)
            mma16816(acc[mt][nt], ahi[mt], &bhi[nt >> 1][(nt & 1) * 2]);
    #pragma unroll
    for (int mt = 0; mt < 2; mt++)
        #pragma unroll
        for (int nt = 0; nt < 4; nt++)
            mma16816h(C[mt][nt], alo[mt], &bhi[nt >> 1][(nt & 1) * 2]);
    #pragma unroll
    for (int mt = 0; mt < 2; mt++)
        #pragma unroll
        for (int nt = 0; nt < 4; nt++)
            mma16816h(C[mt][nt], ahi[mt], &blo[nt >> 1][(nt & 1) * 2]);
}

// ---------------------------------------------------------------------------
// Layer 0: x -> 512 with jet init, interleaved hi/lo fp16 output.
// ---------------------------------------------------------------------------
__global__ void k_layer0(const float* __restrict__ xi, const float* __restrict__ xb,
                         const float* __restrict__ W0, const float* __restrict__ b0)
{
    const int p = blockIdx.x;
    const int j = threadIdx.x * 2;

    float w0a = W0[j],       w0b = W0[j+1];
    float w1a = W0[HID + j], w1b = W0[HID + j + 1];
    float b0a = b0[j],       b0b = b0[j+1];

    if (p < N_INT) {
        float x0 = xi[2*p], x1 = xi[2*p+1];
        float va = fmaf(x0, w0a, fmaf(x1, w1a, b0a));
        float vb = fmaf(x0, w0b, fmaf(x1, w1b, b0b));
        float ya = tanhf(va), yb = tanhf(vb);
        float sa = 1.0f - ya*ya, sb = 1.0f - yb*yb;
        float vals[4][2] = {
            { ya, yb },
            { sa * w0a, sb * w0b },
            { sa * w1a, sb * w1b },
            { -2.0f*ya*sa*(w0a*w0a + w1a*w1a), -2.0f*yb*sb*(w0b*w0b + w1b*w1b) }
        };
        #pragma unroll
        for (int t = 0; t < 4; t++) {
            uint32_t h0, l0, h1, l1;
            hsplit(vals[t][0], h0, l0);
            hsplit(vals[t][1], h1, l1);
            size_t off = (size_t)(4*p + t) * HID + j;
            *(uint32_t*)&g_Ahi[off] = h0 | (h1 << 16);
            *(uint32_t*)&g_Alo[off] = l0 | (l1 << 16);
        }
    } else {
        int q = p - N_INT;
        float x0 = xb[2*q], x1 = xb[2*q+1];
        float va = fmaf(x0, w0a, fmaf(x1, w1a, b0a));
        float vb = fmaf(x0, w0b, fmaf(x1, w1b, b0b));
        float ya = tanhf(va), yb = tanhf(vb);
        uint32_t h0, l0, h1, l1;
        hsplit(ya, h0, l0);
        hsplit(yb, h1, l1);
        size_t off = (size_t)(BROW + q) * HID + j;
        *(uint32_t*)&g_Ahi[off] = h0 | (h1 << 16);
        *(uint32_t*)&g_Alo[off] = l0 | (l1 << 16);
    }
}

// ---------------------------------------------------------------------------
// Weight transpose + fp16 split: Wt*[n][k] = split(W[k][n])
// ---------------------------------------------------------------------------
template<int WHICH>
__global__ void k_transpose(const float* __restrict__ W)
{
    __half* __restrict__ Whi = (WHICH == 1) ? g_W1hi : g_W2hi;
    __half* __restrict__ Wlo = (WHICH == 1) ? g_W1lo : g_W2lo;
    __shared__ float ts[32][33];
    int n0 = blockIdx.x * 32, k0 = blockIdx.y * 32;
    ts[threadIdx.y][threadIdx.x] = W[(size_t)(k0 + threadIdx.y) * HID + n0 + threadIdx.x];
    __syncthreads();
    float v = ts[threadIdx.x][threadIdx.y];   // = W[k0+tx][n0+ty]
    uint32_t h, l;
    hsplit(v, h, l);
    size_t off = (size_t)(n0 + threadIdx.y) * HID + k0 + threadIdx.x;
    Whi[off] = __ushort_as_half((unsigned short)h);
    Wlo[off] = __ushort_as_half((unsigned short)l);
}

// ---------------------------------------------------------------------------
// fp16 split GEMM: main term f32-acc + scaled corrections f16-acc,
// fused bias/tanh-jet epilogue. BM=64, BN=128, BK=32, 256 thr (8 warps),
// 3-stage cp.async pipeline, 2 CTAs/SM.
// MODE 1: jet(A @ W1 + b1) -> g_A2hi/lo ; MODE 2: -> g_S / g_Yb.
// ---------------------------------------------------------------------------
template<int MODE>
__global__ __launch_bounds__(256, 2)
void k_mma(const float* __restrict__ bias)
{
    const __half* __restrict__ Ahi = (MODE == 1) ? g_Ahi : g_A2hi;
    const __half* __restrict__ Alo = (MODE == 1) ? g_Alo : g_A2lo;
    const __half* __restrict__ Whi = (MODE == 1) ? g_W1hi : g_W2hi;
    const __half* __restrict__ Wlo = (MODE == 1) ? g_W1lo : g_W2lo;

    extern __shared__ char smem[];
    const uint32_t sbase = smem_u32(smem);

    const int tid  = threadIdx.x;
    const int lane = tid & 31;
    const int wid  = tid >> 5;        // 0..7
    const int wm   = wid >> 2;        // 0..1 : rows wm*32
    const int wn   = wid & 3;         // 0..3 : cols wn*32
    const int row0 = blockIdx.y * 64;
    const int col0 = blockIdx.x * 128;

    // ldmatrix lane offsets (in halves)
    const int grp = lane >> 3, idx = lane & 7;
    const int aoff = ((grp & 1) * 8 + idx) * SROW + (grp >> 1) * 8;
    const int boff = ((grp >> 1) * 8 + idx) * SROW + (grp & 1) * 8;

    float acc[2][4][4];
    uint32_t C[2][4][2];
    #pragma unroll
    for (int mt = 0; mt < 2; mt++)
        #pragma unroll
        for (int nt = 0; nt < 4; nt++) {
            #pragma unroll
            for (int q = 0; q < 4; q++) acc[mt][nt][q] = 0.0f;
            C[mt][nt][0] = 0u; C[mt][nt][1] = 0u;
        }

    // prefetch: A 1x16B/thread per array, B 2x16B/thread per array
    const int ar = tid >> 2;            // 0..63
    const int ac = (tid & 3) * 8;       // 0,8,16,24 halves
    const int br = tid >> 1;            // 0..127
    const int bc = (tid & 1) * 16;      // 0 or 16 halves
    auto prefetch = [&](int c) {
        uint32_t st = sbase + (uint32_t)(c % NSTAGE) * STAGE;
        size_t ga = (size_t)(row0 + ar) * HID + c * 32 + ac;
        size_t gb = (size_t)(col0 + br) * HID + c * 32 + bc;
        uint32_t oa = (uint32_t)(ar * SROW + ac) * 2;
        uint32_t ob = (uint32_t)(br * SROW + bc) * 2;
        cp16(st + SM_AHI + oa, Ahi + ga);
        cp16(st + SM_ALO + oa, Alo + ga);
        cp16(st + SM_BHI + ob,      Whi + gb);
        cp16(st + SM_BHI + ob + 16, Whi + gb + 8);
        cp16(st + SM_BLO + ob,      Wlo + gb);
        cp16(st + SM_BLO + ob + 16, Wlo + gb + 8);
        asm volatile("cp.async.commit_group;" ::: "memory");
    };

    prefetch(0);
    prefetch(1);

    uint32_t fa_hi[2][2][4], fa_lo[2][2][4], fb_hi[2][2][4], fb_lo[2][2][4];

    for (int c = 0; c < NCH; c++) {
        if (c == NCH - 1) asm volatile("cp.async.wait_group 0;" ::: "memory");
        else              asm volatile("cp.async.wait_group 1;" ::: "memory");
        __syncthreads();
        // After this barrier every warp has finished its ldmatrix reads of
        // chunk c-1 (program order), so stage (c+2)%3 == (c-1)%3 is reusable.
        if (c + 2 < NCH) prefetch(c + 2);

        const uint32_t cur = sbase + (uint32_t)(c % NSTAGE) * STAGE;
        load_frags(cur, 0, wm, wn, aoff, boff, fa_hi[0], fa_lo[0], fb_hi[0], fb_lo[0]);
        load_frags(cur, 1, wm, wn, aoff, boff, fa_hi[1], fa_lo[1], fb_hi[1], fb_lo[1]);
        do_mmas(acc, C, fa_hi[0], fa_lo[0], fb_hi[0], fb_lo[0]);
        do_mmas(acc, C, fa_hi[1], fa_lo[1], fb_hi[1], fb_lo[1]);
        // no trailing __syncthreads needed (see comment above)
    }

    // ---- fold scaled corrections into the fp32 accumulators ----
    #pragma unroll
    for (int mt = 0; mt < 2; mt++)
        #pragma unroll
        for (int nt = 0; nt < 4; nt++) {
            float2 c01 = __half22float2(*(__half2*)&C[mt][nt][0]);
            float2 c23 = __half22float2(*(__half2*)&C[mt][nt][1]);
            acc[mt][nt][0] = fmaf(c01.x, INV_LO_SCALE, acc[mt][nt][0]);
            acc[mt][nt][1] = fmaf(c01.y, INV_LO_SCALE, acc[mt][nt][1]);
            acc[mt][nt][2] = fmaf(c23.x, INV_LO_SCALE, acc[mt][nt][2]);
            acc[mt][nt][3] = fmaf(c23.y, INV_LO_SCALE, acc[mt][nt][3]);
        }

    // ---- epilogue: bias + tanh-jet ----
    float bb[4][2];
    #pragma unroll
    for (int nt = 0; nt < 4; nt++)
        #pragma unroll
        for (int j = 0; j < 2; j++)
            bb[nt][j] = __ldg(&bias[col0 + wn*32 + nt*8 + (lane & 3)*2 + j]);

    const int role = (lane >> 2) & 3;
    const int srcL = (lane & ~15) | (lane & 3);

    if (blockIdx.y < INT_TILES) {
        #pragma unroll
        for (int mt = 0; mt < 2; mt++)
            #pragma unroll
            for (int h = 0; h < 2; h++) {
                const int grow = row0 + wm*32 + mt*16 + (lane >> 2) + 8*h;
                #pragma unroll
                for (int nt = 0; nt < 4; nt++) {
                    float o[2];
                    #pragma unroll
                    for (int j = 0; j < 2; j++) {
                        float x  = acc[mt][nt][h*2 + j];
                        float v  = __shfl_sync(0xFFFFFFFFu, x, srcL);
                        float p0 = __shfl_sync(0xFFFFFFFFu, x, srcL + 4);
                        float p1 = __shfl_sync(0xFFFFFFFFu, x, srcL + 8);
                        float y  = tanhf(v + bb[nt][j]);
                        float s  = 1.0f - y*y;
                        float r;
                        if      (role == 0) r = y;
                        else if (role == 1) r = s * p0;
                        else if (role == 2) r = s * p1;
                        else                r = fmaf(s, x, -2.0f * y * s * (p0*p0 + p1*p1));
                        o[j] = r;
                    }
                    const int colb = col0 + wn*32 + nt*8 + (lane & 3)*2;
                    if (MODE == 1) {
                        uint32_t h0, l0, h1, l1;
                        hsplit(o[0], h0, l0);
                        hsplit(o[1], h1, l1);
                        size_t off = (size_t)grow * HID + colb;
                        *(uint32_t*)&g_A2hi[off] = h0 | (h1 << 16);
                        *(uint32_t*)&g_A2lo[off] = l0 | (l1 << 16);
                    } else if (role == 3) {
                        *(float2*)&g_S[(size_t)(grow >> 2) * HID + colb] = make_float2(o[0], o[1]);
                    }
                }
            }
    } else {
        #pragma unroll
        for (int mt = 0; mt < 2; mt++)
            #pragma unroll
            for (int h = 0; h < 2; h++) {
                const int grow = row0 + wm*32 + mt*16 + (lane >> 2) + 8*h;
                if (grow < M_ROWS) {
                    #pragma unroll
                    for (int nt = 0; nt < 4; nt++) {
                        float o0 = tanhf(acc[mt][nt][h*2 + 0] + bb[nt][0]);
                        float o1 = tanhf(acc[mt][nt][h*2 + 1] + bb[nt][1]);
                        const int colb = col0 + wn*32 + nt*8 + (lane & 3)*2;
                        if (MODE == 1) {
                            uint32_t h0, l0, h1, l1;
                            hsplit(o0, h0, l0);
                            hsplit(o1, h1, l1);
                            size_t off = (size_t)grow * HID + colb;
                            *(uint32_t*)&g_A2hi[off] = h0 | (h1 << 16);
                            *(uint32_t*)&g_A2lo[off] = l0 | (l1 << 16);
                        } else {
                            *(float2*)&g_Yb[(size_t)(grow - BROW) * HID + colb] = make_float2(o0, o1);
                        }
                    }
                }
            }
    }
}

// ---------------------------------------------------------------------------
// Final reductions (unchanged, proven).
// ---------------------------------------------------------------------------
__global__ void k_final_interior(const float* __restrict__ xi, const float* __restrict__ W3)
{
    int warp = threadIdx.x >> 5;
    int lane = threadIdx.x & 31;
    int p = blockIdx.x * 8 + warp;

    float val = 0.0f;
    if (p < N_INT) {
        const float* row = &g_S[(size_t)p * HID];
        float acc = 0.0f;
        #pragma unroll 4
        for (int j = lane; j < HID; j += 32) acc = fmaf(row[j], W3[j], acc);
        #pragma unroll
        for (int o = 16; o; o >>= 1) acc += __shfl_xor_sync(0xFFFFFFFFu, acc, o);
        if (lane == 0) {
            const float PI = 3.14159265358979323846f;
            float xx = xi[2*p], yy = xi[2*p+1];
            float sy2 = sinf(PI*yy*yy), cy2 = cosf(PI*yy*yy), sx = sinf(PI*xx);
            float f = -PI*PI*(1.0f + 4.0f*yy*yy)*sx*sy2 + 2.0f*PI*sx*cy2;
            float r = acc - f;
            val = r * r;
        }
    }
    __shared__ float sh[8];
    if (lane == 0) sh[warp] = val;
    __syncthreads();
    if (threadIdx.x == 0) {
        float s = 0.0f;
        #pragma unroll
        for (int i = 0; i < 8; i++) s += sh[i];
        g_partial_i[blockIdx.x] = s;
    }
}

__global__ void k_final_boundary(const float* __restrict__ W3, const float* __restrict__ b3)
{
    int warp = threadIdx.x >> 5;
    int lane = threadIdx.x & 31;
    int p = blockIdx.x * 8 + warp;

    float val = 0.0f;
    if (p < N_B) {
        const float* row = &g_Yb[(size_t)p * HID];
        float acc = 0.0f;
        #pragma unroll 4
        for (int j = lane; j < HID; j += 32) acc = fmaf(row[j], W3[j], acc);
        #pragma unroll
        for (int o = 16; o; o >>= 1) acc += __shfl_xor_sync(0xFFFFFFFFu, acc, o);
        if (lane == 0) {
            float u = acc + b3[0];
            val = u * u;
        }
    }
    __shared__ float sh[8];
    if (lane == 0) sh[warp] = val;
    __syncthreads();
    if (threadIdx.x == 0) {
        float s = 0.0f;
        #pragma unroll
        for (int i = 0; i < 8; i++) s += sh[i];
        g_partial_b[blockIdx.x] = s;
    }
}

__global__ void k_combine(float* __restrict__ out)
{
    __shared__ float sh[256];
    int t = threadIdx.x;

    float si = 0.0f;
    for (int i = t; i < 2500; i += 256) si += g_partial_i[i];
    sh[t] = si;
    __syncthreads();
    for (int o = 128; o; o >>= 1) { if (t < o) sh[t] += sh[t + o]; __syncthreads(); }
    float interior_sum = sh[0];
    __syncthreads();

    float sb = 0.0f;
    for (int i = t; i < 100; i += 256) sb += g_partial_b[i];
    sh[t] = sb;
    __syncthreads();
    for (int o = 128; o; o >>= 1) { if (t < o) sh[t] += sh[t + o]; __syncthreads(); }

    if (t == 0) {
        float interior_loss = interior_sum / (float)N_INT;
        float boundary_loss = sh[0] / (float)N_B;
        out[0] = ALPHA * interior_loss + boundary_loss;
        out[1] = interior_loss;
        out[2] = boundary_loss;
    }
}

// ---------------------------------------------------------------------------
extern "C" void kernel_launch(void* const* d_in, const int* in_sizes, int n_in,
                              void* d_out, int out_size)
{
    const float* xi = (const float*)d_in[0];
    const float* xb = (const float*)d_in[1];
    const float* W0 = (const float*)d_in[2];
    const float* b0 = (const float*)d_in[3];
    const float* W1 = (const float*)d_in[4];
    const float* b1 = (const float*)d_in[5];
    const float* W2 = (const float*)d_in[6];
    const float* b2 = (const float*)d_in[7];
    const float* W3 = (const float*)d_in[8];
    const float* b3 = (const float*)d_in[9];

    cudaFuncSetAttribute(k_mma<1>, cudaFuncAttributeMaxDynamicSharedMemorySize, SMEM_DYN);
    cudaFuncSetAttribute(k_mma<2>, cudaFuncAttributeMaxDynamicSharedMemorySize, SMEM_DYN);

    dim3 tgrid(16, 16), tblock(32, 32);
    dim3 mma_grid(4, M_TILES);

    k_layer0<<<N_INT + N_B, 256>>>(xi, xb, W0, b0);
    k_transpose<1><<<tgrid, tblock>>>(W1);
    k_transpose<2><<<tgrid, tblock>>>(W2);
    k_mma<1><<<mma_grid, 256, SMEM_DYN>>>(b1);
    k_mma<2><<<mma_grid, 256, SMEM_DYN>>>(b2);
    k_final_interior<<<(N_INT + 7) / 8, 256>>>(xi, W3);
    k_final_boundary<<<(N_B + 7) / 8, 256>>>(W3, b3);
    k_combine<<<1, 256>>>((float*)d_out);
}

// round 16
// speedup vs baseline: 1.2434x; 1.2434x over previous
#include <cuda_runtime.h>
#include <cuda_fp16.h>
#include <math.h>
#include <stdint.h>

#define N_INT 20000
#define N_B   800
#define HID   512
#define BROW  (4*N_INT)              // 80000
#define M_ROWS (BROW + N_B)          // 80800
#define M_TILES 632                  // ceil(80800/128)
#define INT_TILES 625                // 80000/128 : tiles below are pure interior
#define M_PAD (M_TILES*128)          // 80896 (pad rows stay zero forever)
#define ALPHA 0.01f
#define NCH 16                       // 512/32 k-chunks

// smem per stage: Ahi/Alo/Bhi/Blo, each 128 rows x 40 halves (pad -> ldmatrix conflict-free)
#define SROW 40
#define SM_AHI 0
#define SM_ALO 10240
#define SM_BHI 20480
#define SM_BLO 30720
#define STAGE  40960
#define NSTAGE 2
#define SMEM_DYN (NSTAGE*STAGE)      // 81920 B -> 2 CTAs/SM

// Activations as hi/lo fp16 pairs (Markidis split). Ping-pong A -> A2.
__device__ __half g_Ahi [(size_t)M_PAD * HID];
__device__ __half g_Alo [(size_t)M_PAD * HID];
__device__ __half g_A2hi[(size_t)M_PAD * HID];
__device__ __half g_A2lo[(size_t)M_PAD * HID];
__device__ __half g_W1hi[HID * HID];   // [n][k]
__device__ __half g_W1lo[HID * HID];
__device__ __half g_W2hi[HID * HID];
__device__ __half g_W2lo[HID * HID];
__device__ float  g_S [(size_t)N_INT * HID];
__device__ float  g_Yb[(size_t)N_B * HID];
__device__ float  g_partial_i[2500];
__device__ float  g_partial_b[100];

// ------------------------------- helpers -----------------------------------
static __device__ __forceinline__ uint32_t smem_u32(const void* p) {
    uint32_t a;
    asm("{ .reg .u64 t; cvta.to.shared.u64 t, %1; cvt.u32.u64 %0, t; }" : "=r"(a) : "l"(p));
    return a;
}
static __device__ __forceinline__ void cp16(uint32_t dst, const void* src) {
    asm volatile("cp.async.cg.shared.global [%0], [%1], 16;" :: "r"(dst), "l"(src));
}
static __device__ __forceinline__ void ldsm4(uint32_t* r, uint32_t addr) {
    asm volatile("ldmatrix.sync.aligned.m8n8.x4.shared.b16 {%0,%1,%2,%3}, [%4];"
                 : "=r"(r[0]), "=r"(r[1]), "=r"(r[2]), "=r"(r[3]) : "r"(addr));
}
static __device__ __forceinline__ void mma16816(float* d, const uint32_t* a, const uint32_t* b) {
    asm volatile(
        "mma.sync.aligned.m16n8k16.row.col.f32.f16.f16.f32 "
        "{%0,%1,%2,%3}, {%4,%5,%6,%7}, {%8,%9}, {%0,%1,%2,%3};"
        : "+f"(d[0]), "+f"(d[1]), "+f"(d[2]), "+f"(d[3])
        : "r"(a[0]), "r"(a[1]), "r"(a[2]), "r"(a[3]), "r"(b[0]), "r"(b[1]));
}
static __device__ __forceinline__ void hsplit(float x, uint32_t& h, uint32_t& l) {
    __half hh = __float2half_rn(x);
    float  r  = x - __half2float(hh);
    __half ll = __float2half_rn(r);
    h = __half_as_ushort(hh);
    l = __half_as_ushort(ll);
}

// ---------------------------------------------------------------------------
// Layer 0: x -> 512 with jet init, interleaved hi/lo fp16 output.
// ---------------------------------------------------------------------------
__global__ void k_layer0(const float* __restrict__ xi, const float* __restrict__ xb,
                         const float* __restrict__ W0, const float* __restrict__ b0)
{
    const int p = blockIdx.x;
    const int j = threadIdx.x * 2;

    float w0a = W0[j],       w0b = W0[j+1];
    float w1a = W0[HID + j], w1b = W0[HID + j + 1];
    float b0a = b0[j],       b0b = b0[j+1];

    if (p < N_INT) {
        float x0 = xi[2*p], x1 = xi[2*p+1];
        float va = fmaf(x0, w0a, fmaf(x1, w1a, b0a));
        float vb = fmaf(x0, w0b, fmaf(x1, w1b, b0b));
        float ya = tanhf(va), yb = tanhf(vb);
        float sa = 1.0f - ya*ya, sb = 1.0f - yb*yb;
        float vals[4][2] = {
            { ya, yb },
            { sa * w0a, sb * w0b },
            { sa * w1a, sb * w1b },
            { -2.0f*ya*sa*(w0a*w0a + w1a*w1a), -2.0f*yb*sb*(w0b*w0b + w1b*w1b) }
        };
        #pragma unroll
        for (int t = 0; t < 4; t++) {
            uint32_t h0, l0, h1, l1;
            hsplit(vals[t][0], h0, l0);
            hsplit(vals[t][1], h1, l1);
            size_t off = (size_t)(4*p + t) * HID + j;
            *(uint32_t*)&g_Ahi[off] = h0 | (h1 << 16);
            *(uint32_t*)&g_Alo[off] = l0 | (l1 << 16);
        }
    } else {
        int q = p - N_INT;
        float x0 = xb[2*q], x1 = xb[2*q+1];
        float va = fmaf(x0, w0a, fmaf(x1, w1a, b0a));
        float vb = fmaf(x0, w0b, fmaf(x1, w1b, b0b));
        float ya = tanhf(va), yb = tanhf(vb);
        uint32_t h0, l0, h1, l1;
        hsplit(ya, h0, l0);
        hsplit(yb, h1, l1);
        size_t off = (size_t)(BROW + q) * HID + j;
        *(uint32_t*)&g_Ahi[off] = h0 | (h1 << 16);
        *(uint32_t*)&g_Alo[off] = l0 | (l1 << 16);
    }
}

// ---------------------------------------------------------------------------
// Weight transpose + fp16 split: Wt*[n][k] = split(W[k][n])
// ---------------------------------------------------------------------------
template<int WHICH>
__global__ void k_transpose(const float* __restrict__ W)
{
    __half* __restrict__ Whi = (WHICH == 1) ? g_W1hi : g_W2hi;
    __half* __restrict__ Wlo = (WHICH == 1) ? g_W1lo : g_W2lo;
    __shared__ float ts[32][33];
    int n0 = blockIdx.x * 32, k0 = blockIdx.y * 32;
    ts[threadIdx.y][threadIdx.x] = W[(size_t)(k0 + threadIdx.y) * HID + n0 + threadIdx.x];
    __syncthreads();
    float v = ts[threadIdx.x][threadIdx.y];   // = W[k0+tx][n0+ty]
    uint32_t h, l;
    hsplit(v, h, l);
    size_t off = (size_t)(n0 + threadIdx.y) * HID + k0 + threadIdx.x;
    Whi[off] = __ushort_as_half((unsigned short)h);
    Wlo[off] = __ushort_as_half((unsigned short)l);
}

// ---------------------------------------------------------------------------
// fp16 3-split GEMM via mma.sync + fused bias/tanh-jet epilogue.
// BM=128, BN=128, BK=32, 256 thr, 8 warps in 2x4 grid, warp tile 64x32
// (4 M-tiles share each B fragment: -25% LDSM traffic vs 32x32).
// 2-stage cp.async pipeline, 2 CTAs/SM.
// MODE 1: jet(A @ W1 + b1) -> g_A2hi/lo ; MODE 2: -> g_S / g_Yb.
// ---------------------------------------------------------------------------
template<int MODE>
__global__ __launch_bounds__(256, 2)
void k_mma(const float* __restrict__ bias)
{
    const __half* __restrict__ Ahi = (MODE == 1) ? g_Ahi : g_A2hi;
    const __half* __restrict__ Alo = (MODE == 1) ? g_Alo : g_A2lo;
    const __half* __restrict__ Whi = (MODE == 1) ? g_W1hi : g_W2hi;
    const __half* __restrict__ Wlo = (MODE == 1) ? g_W1lo : g_W2lo;

    extern __shared__ char smem[];
    const uint32_t sbase = smem_u32(smem);

    const int tid  = threadIdx.x;
    const int lane = tid & 31;
    const int wid  = tid >> 5;        // 0..7
    const int wm   = wid >> 2;        // 0..1 : rows wm*64
    const int wn   = wid & 3;         // 0..3 : cols wn*32
    const int row0 = blockIdx.y * 128;
    const int col0 = blockIdx.x * 128;

    // ldmatrix lane offsets (in halves)
    const int grp = lane >> 3, idx = lane & 7;
    const int aoff = ((grp & 1) * 8 + idx) * SROW + (grp >> 1) * 8;
    const int boff = ((grp >> 1) * 8 + idx) * SROW + (grp & 1) * 8;

    float acc[4][4][4];
    #pragma unroll
    for (int mt = 0; mt < 4; mt++)
        #pragma unroll
        for (int nt = 0; nt < 4; nt++)
            #pragma unroll
            for (int q = 0; q < 4; q++) acc[mt][nt][q] = 0.0f;

    // prefetch: 128 rows x 32 data halves per array; 2 threads/row, 2 cp16 each
    const int fr = tid >> 1;            // 0..127
    const int fc = (tid & 1) * 16;      // 0 or 16 halves
    auto prefetch = [&](int c) {
        uint32_t st = sbase + (uint32_t)(c & 1) * STAGE;
        size_t ga = (size_t)(row0 + fr) * HID + c * 32 + fc;
        size_t gb = (size_t)(col0 + fr) * HID + c * 32 + fc;
        uint32_t o = (uint32_t)(fr * SROW + fc) * 2;
        cp16(st + SM_AHI + o,      Ahi + ga);
        cp16(st + SM_AHI + o + 16, Ahi + ga + 8);
        cp16(st + SM_ALO + o,      Alo + ga);
        cp16(st + SM_ALO + o + 16, Alo + ga + 8);
        cp16(st + SM_BHI + o,      Whi + gb);
        cp16(st + SM_BHI + o + 16, Whi + gb + 8);
        cp16(st + SM_BLO + o,      Wlo + gb);
        cp16(st + SM_BLO + o + 16, Wlo + gb + 8);
        asm volatile("cp.async.commit_group;" ::: "memory");
    };

    prefetch(0);
    prefetch(1);

    for (int c = 0; c < NCH; c++) {
        if (c == NCH - 1) asm volatile("cp.async.wait_group 0;" ::: "memory");
        else              asm volatile("cp.async.wait_group 1;" ::: "memory");
        __syncthreads();

        const uint32_t cur = sbase + (uint32_t)(c & 1) * STAGE;
        #pragma unroll
        for (int ks = 0; ks < 2; ks++) {
            uint32_t ahi[4][4], alo[4][4], bhi[2][4], blo[2][4];
            #pragma unroll
            for (int mt = 0; mt < 4; mt++) {
                uint32_t base = cur + 2u * ((wm*64 + mt*16) * SROW + ks*16 + aoff);
                ldsm4(ahi[mt], base + SM_AHI);
                ldsm4(alo[mt], base + SM_ALO);
            }
            #pragma unroll
            for (int np = 0; np < 2; np++) {
                uint32_t base = cur + 2u * ((wn*32 + np*16) * SROW + ks*16 + boff);
                ldsm4(bhi[np], base + SM_BHI);
                ldsm4(blo[np], base + SM_BLO);
            }
            // hh pass, then lh, then hl (same-acc MMAs far apart; order preserved)
            #pragma unroll
            for (int mt = 0; mt < 4; mt++)
                #pragma unroll
                for (int nt = 0; nt < 4; nt++)
                    mma16816(acc[mt][nt], ahi[mt], &bhi[nt >> 1][(nt & 1) * 2]);
            #pragma unroll
            for (int mt = 0; mt < 4; mt++)
                #pragma unroll
                for (int nt = 0; nt < 4; nt++)
                    mma16816(acc[mt][nt], alo[mt], &bhi[nt >> 1][(nt & 1) * 2]);
            #pragma unroll
            for (int mt = 0; mt < 4; mt++)
                #pragma unroll
                for (int nt = 0; nt < 4; nt++)
                    mma16816(acc[mt][nt], ahi[mt], &blo[nt >> 1][(nt & 1) * 2]);
        }

        if (c + 2 < NCH) {
            __syncthreads();             // all warps done reading stage c&1
            prefetch(c + 2);             // safe to overwrite it now
        }
    }

    // ---- epilogue: bias + tanh-jet ----
    float bb[4][2];
    #pragma unroll
    for (int nt = 0; nt < 4; nt++)
        #pragma unroll
        for (int j = 0; j < 2; j++)
            bb[nt][j] = __ldg(&bias[col0 + wn*32 + nt*8 + (lane & 3)*2 + j]);

    const int role = (lane >> 2) & 3;
    const int srcL = (lane & ~15) | (lane & 3);

    if (blockIdx.y < INT_TILES) {
        #pragma unroll
        for (int mt = 0; mt < 4; mt++)
            #pragma unroll
            for (int h = 0; h < 2; h++) {
                const int grow = row0 + wm*64 + mt*16 + (lane >> 2) + 8*h;
                #pragma unroll
                for (int nt = 0; nt < 4; nt++) {
                    float o[2];
                    #pragma unroll
                    for (int j = 0; j < 2; j++) {
                        float x  = acc[mt][nt][h*2 + j];
                        float v  = __shfl_sync(0xFFFFFFFFu, x, srcL);
                        float p0 = __shfl_sync(0xFFFFFFFFu, x, srcL + 4);
                        float p1 = __shfl_sync(0xFFFFFFFFu, x, srcL + 8);
                        float y  = tanhf(v + bb[nt][j]);
                        float s  = 1.0f - y*y;
                        float r;
                        if      (role == 0) r = y;
                        else if (role == 1) r = s * p0;
                        else if (role == 2) r = s * p1;
                        else                r = fmaf(s, x, -2.0f * y * s * (p0*p0 + p1*p1));
                        o[j] = r;
                    }
                    const int colb = col0 + wn*32 + nt*8 + (lane & 3)*2;
                    if (MODE == 1) {
                        uint32_t h0, l0, h1, l1;
                        hsplit(o[0], h0, l0);
                        hsplit(o[1], h1, l1);
                        size_t off = (size_t)grow * HID + colb;
                        *(uint32_t*)&g_A2hi[off] = h0 | (h1 << 16);
                        *(uint32_t*)&g_A2lo[off] = l0 | (l1 << 16);
                    } else if (role == 3) {
                        *(float2*)&g_S[(size_t)(grow >> 2) * HID + colb] = make_float2(o[0], o[1]);
                    }
                }
            }
    } else {
        #pragma unroll
        for (int mt = 0; mt < 4; mt++)
            #pragma unroll
            for (int h = 0; h < 2; h++) {
                const int grow = row0 + wm*64 + mt*16 + (lane >> 2) + 8*h;
                if (grow < M_ROWS) {
                    #pragma unroll
                    for (int nt = 0; nt < 4; nt++) {
                        float o0 = tanhf(acc[mt][nt][h*2 + 0] + bb[nt][0]);
                        float o1 = tanhf(acc[mt][nt][h*2 + 1] + bb[nt][1]);
                        const int colb = col0 + wn*32 + nt*8 + (lane & 3)*2;
                        if (MODE == 1) {
                            uint32_t h0, l0, h1, l1;
                            hsplit(o0, h0, l0);
                            hsplit(o1, h1, l1);
                            size_t off = (size_t)grow * HID + colb;
                            *(uint32_t*)&g_A2hi[off] = h0 | (h1 << 16);
                            *(uint32_t*)&g_A2lo[off] = l0 | (l1 << 16);
                        } else {
                            *(float2*)&g_Yb[(size_t)(grow - BROW) * HID + colb] = make_float2(o0, o1);
                        }
                    }
                }
            }
    }
}

// ---------------------------------------------------------------------------
// Final reductions (unchanged, proven).
// ---------------------------------------------------------------------------
__global__ void k_final_interior(const float* __restrict__ xi, const float* __restrict__ W3)
{
    int warp = threadIdx.x >> 5;
    int lane = threadIdx.x & 31;
    int p = blockIdx.x * 8 + warp;

    float val = 0.0f;
    if (p < N_INT) {
        const float* row = &g_S[(size_t)p * HID];
        float acc = 0.0f;
        #pragma unroll 4
        for (int j = lane; j < HID; j += 32) acc = fmaf(row[j], W3[j], acc);
        #pragma unroll
        for (int o = 16; o; o >>= 1) acc += __shfl_xor_sync(0xFFFFFFFFu, acc, o);
        if (lane == 0) {
            const float PI = 3.14159265358979323846f;
            float xx = xi[2*p], yy = xi[2*p+1];
            float sy2 = sinf(PI*yy*yy), cy2 = cosf(PI*yy*yy), sx = sinf(PI*xx);
            float f = -PI*PI*(1.0f + 4.0f*yy*yy)*sx*sy2 + 2.0f*PI*sx*cy2;
            float r = acc - f;
            val = r * r;
        }
    }
    __shared__ float sh[8];
    if (lane == 0) sh[warp] = val;
    __syncthreads();
    if (threadIdx.x == 0) {
        float s = 0.0f;
        #pragma unroll
        for (int i = 0; i < 8; i++) s += sh[i];
        g_partial_i[blockIdx.x] = s;
    }
}

__global__ void k_final_boundary(const float* __restrict__ W3, const float* __restrict__ b3)
{
    int warp = threadIdx.x >> 5;
    int lane = threadIdx.x & 31;
    int p = blockIdx.x * 8 + warp;

    float val = 0.0f;
    if (p < N_B) {
        const float* row = &g_Yb[(size_t)p * HID];
        float acc = 0.0f;
        #pragma unroll 4
        for (int j = lane; j < HID; j += 32) acc = fmaf(row[j], W3[j], acc);
        #pragma unroll
        for (int o = 16; o; o >>= 1) acc += __shfl_xor_sync(0xFFFFFFFFu, acc, o);
        if (lane == 0) {
            float u = acc + b3[0];
            val = u * u;
        }
    }
    __shared__ float sh[8];
    if (lane == 0) sh[warp] = val;
    __syncthreads();
    if (threadIdx.x == 0) {
        float s = 0.0f;
        #pragma unroll
        for (int i = 0; i < 8; i++) s += sh[i];
        g_partial_b[blockIdx.x] = s;
    }
}

__global__ void k_combine(float* __restrict__ out)
{
    __shared__ float sh[256];
    int t = threadIdx.x;

    float si = 0.0f;
    for (int i = t; i < 2500; i += 256) si += g_partial_i[i];
    sh[t] = si;
    __syncthreads();
    for (int o = 128; o; o >>= 1) { if (t < o) sh[t] += sh[t + o]; __syncthreads(); }
    float interior_sum = sh[0];
    __syncthreads();

    float sb = 0.0f;
    for (int i = t; i < 100; i += 256) sb += g_partial_b[i];
    sh[t] = sb;
    __syncthreads();
    for (int o = 128; o; o >>= 1) { if (t < o) sh[t] += sh[t + o]; __syncthreads(); }

    if (t == 0) {
        float interior_loss = interior_sum / (float)N_INT;
        float boundary_loss = sh[0] / (float)N_B;
        out[0] = ALPHA * interior_loss + boundary_loss;
        out[1] = interior_loss;
        out[2] = boundary_loss;
    }
}

// ---------------------------------------------------------------------------
extern "C" void kernel_launch(void* const* d_in, const int* in_sizes, int n_in,
                              void* d_out, int out_size)
{
    const float* xi = (const float*)d_in[0];
    const float* xb = (const float*)d_in[1];
    const float* W0 = (const float*)d_in[2];
    const float* b0 = (const float*)d_in[3];
    const float* W1 = (const float*)d_in[4];
    const float* b1 = (const float*)d_in[5];
    const float* W2 = (const float*)d_in[6];
    const float* b2 = (const float*)d_in[7];
    const float* W3 = (const float*)d_in[8];
    const float* b3 = (const float*)d_in[9];

    cudaFuncSetAttribute(k_mma<1>, cudaFuncAttributeMaxDynamicSharedMemorySize, SMEM_DYN);
    cudaFuncSetAttribute(k_mma<2>, cudaFuncAttributeMaxDynamicSharedMemorySize, SMEM_DYN);

    dim3 tgrid(16, 16), tblock(32, 32);
    dim3 mma_grid(4, M_TILES);

    k_layer0<<<N_INT + N_B, 256>>>(xi, xb, W0, b0);
    k_transpose<1><<<tgrid, tblock>>>(W1);
    k_transpose<2><<<tgrid, tblock>>>(W2);
    k_mma<1><<<mma_grid, 256, SMEM_DYN>>>(b1);
    k_mma<2><<<mma_grid, 256, SMEM_DYN>>>(b2);
    k_final_interior<<<(N_INT + 7) / 8, 256>>>(xi, W3);
    k_final_boundary<<<(N_B + 7) / 8, 256>>>(W3, b3);
    k_combine<<<1, 256>>>((float*)d_out);
}

// round 17
// speedup vs baseline: 1.3540x; 1.0889x over previous
#include <cuda_runtime.h>
#include <cuda_fp16.h>
#include <math.h>
#include <stdint.h>

#define N_INT 20000
#define N_B   800
#define HID   512
#define BROW  (4*N_INT)              // 80000
#define M_ROWS (BROW + N_B)          // 80800
#define M_TILES 632                  // ceil(80800/128)
#define INT_TILES 625                // 80000/128 : tiles below are pure interior
#define M_PAD (M_TILES*128)          // 80896 (pad rows stay zero forever)
#define ALPHA 0.01f
#define NCH 16                       // 512/32 k-chunks

// smem per stage: 4 arrays (Ahi/Alo/Bhi/Blo), each 128 rows x 64B,
// XOR-swizzled 16B chunks: chunk' = chunk ^ ((row>>1)&3)  (ldmatrix conflict-free)
#define SM_AHI 0
#define SM_ALO 8192
#define SM_BHI 16384
#define SM_BLO 24576
#define STAGE  32768
#define NSTAGE 3
#define SMEM_DYN (NSTAGE*STAGE)      // 98304 B -> 2 CTAs/SM (196.6 KB of 228)

// Activations as hi/lo fp16 pairs (Markidis split). Ping-pong A -> A2.
__device__ __half g_Ahi [(size_t)M_PAD * HID];
__device__ __half g_Alo [(size_t)M_PAD * HID];
__device__ __half g_A2hi[(size_t)M_PAD * HID];
__device__ __half g_A2lo[(size_t)M_PAD * HID];
__device__ __half g_W1hi[HID * HID];   // [n][k]
__device__ __half g_W1lo[HID * HID];
__device__ __half g_W2hi[HID * HID];
__device__ __half g_W2lo[HID * HID];
__device__ float  g_S [(size_t)N_INT * HID];
__device__ float  g_Yb[(size_t)N_B * HID];
__device__ float  g_partial_i[2500];
__device__ float  g_partial_b[100];

// ------------------------------- helpers -----------------------------------
static __device__ __forceinline__ uint32_t smem_u32(const void* p) {
    uint32_t a;
    asm("{ .reg .u64 t; cvta.to.shared.u64 t, %1; cvt.u32.u64 %0, t; }" : "=r"(a) : "l"(p));
    return a;
}
static __device__ __forceinline__ void cp16(uint32_t dst, const void* src) {
    asm volatile("cp.async.cg.shared.global [%0], [%1], 16;" :: "r"(dst), "l"(src));
}
static __device__ __forceinline__ void ldsm4(uint32_t* r, uint32_t addr) {
    asm volatile("ldmatrix.sync.aligned.m8n8.x4.shared.b16 {%0,%1,%2,%3}, [%4];"
                 : "=r"(r[0]), "=r"(r[1]), "=r"(r[2]), "=r"(r[3]) : "r"(addr));
}
static __device__ __forceinline__ void mma16816(float* d, const uint32_t* a, const uint32_t* b) {
    asm volatile(
        "mma.sync.aligned.m16n8k16.row.col.f32.f16.f16.f32 "
        "{%0,%1,%2,%3}, {%4,%5,%6,%7}, {%8,%9}, {%0,%1,%2,%3};"
        : "+f"(d[0]), "+f"(d[1]), "+f"(d[2]), "+f"(d[3])
        : "r"(a[0]), "r"(a[1]), "r"(a[2]), "r"(a[3]), "r"(b[0]), "r"(b[1]));
}
static __device__ __forceinline__ void hsplit(float x, uint32_t& h, uint32_t& l) {
    __half hh = __float2half_rn(x);
    float  r  = x - __half2float(hh);
    __half ll = __float2half_rn(r);
    h = __half_as_ushort(hh);
    l = __half_as_ushort(ll);
}

// ---------------------------------------------------------------------------
// Layer 0: x -> 512 with jet init, interleaved hi/lo fp16 output.
// ---------------------------------------------------------------------------
__global__ void k_layer0(const float* __restrict__ xi, const float* __restrict__ xb,
                         const float* __restrict__ W0, const float* __restrict__ b0)
{
    const int p = blockIdx.x;
    const int j = threadIdx.x * 2;

    float w0a = W0[j],       w0b = W0[j+1];
    float w1a = W0[HID + j], w1b = W0[HID + j + 1];
    float b0a = b0[j],       b0b = b0[j+1];

    if (p < N_INT) {
        float x0 = xi[2*p], x1 = xi[2*p+1];
        float va = fmaf(x0, w0a, fmaf(x1, w1a, b0a));
        float vb = fmaf(x0, w0b, fmaf(x1, w1b, b0b));
        float ya = tanhf(va), yb = tanhf(vb);
        float sa = 1.0f - ya*ya, sb = 1.0f - yb*yb;
        float vals[4][2] = {
            { ya, yb },
            { sa * w0a, sb * w0b },
            { sa * w1a, sb * w1b },
            { -2.0f*ya*sa*(w0a*w0a + w1a*w1a), -2.0f*yb*sb*(w0b*w0b + w1b*w1b) }
        };
        #pragma unroll
        for (int t = 0; t < 4; t++) {
            uint32_t h0, l0, h1, l1;
            hsplit(vals[t][0], h0, l0);
            hsplit(vals[t][1], h1, l1);
            size_t off = (size_t)(4*p + t) * HID + j;
            *(uint32_t*)&g_Ahi[off] = h0 | (h1 << 16);
            *(uint32_t*)&g_Alo[off] = l0 | (l1 << 16);
        }
    } else {
        int q = p - N_INT;
        float x0 = xb[2*q], x1 = xb[2*q+1];
        float va = fmaf(x0, w0a, fmaf(x1, w1a, b0a));
        float vb = fmaf(x0, w0b, fmaf(x1, w1b, b0b));
        float ya = tanhf(va), yb = tanhf(vb);
        uint32_t h0, l0, h1, l1;
        hsplit(ya, h0, l0);
        hsplit(yb, h1, l1);
        size_t off = (size_t)(BROW + q) * HID + j;
        *(uint32_t*)&g_Ahi[off] = h0 | (h1 << 16);
        *(uint32_t*)&g_Alo[off] = l0 | (l1 << 16);
    }
}

// ---------------------------------------------------------------------------
// Weight transpose + fp16 split: Wt*[n][k] = split(W[k][n])
// ---------------------------------------------------------------------------
template<int WHICH>
__global__ void k_transpose(const float* __restrict__ W)
{
    __half* __restrict__ Whi = (WHICH == 1) ? g_W1hi : g_W2hi;
    __half* __restrict__ Wlo = (WHICH == 1) ? g_W1lo : g_W2lo;
    __shared__ float ts[32][33];
    int n0 = blockIdx.x * 32, k0 = blockIdx.y * 32;
    ts[threadIdx.y][threadIdx.x] = W[(size_t)(k0 + threadIdx.y) * HID + n0 + threadIdx.x];
    __syncthreads();
    float v = ts[threadIdx.x][threadIdx.y];   // = W[k0+tx][n0+ty]
    uint32_t h, l;
    hsplit(v, h, l);
    size_t off = (size_t)(n0 + threadIdx.y) * HID + k0 + threadIdx.x;
    Whi[off] = __ushort_as_half((unsigned short)h);
    Wlo[off] = __ushort_as_half((unsigned short)l);
}

// ---------------------------------------------------------------------------
// fp16 3-split GEMM via mma.sync + fused bias/tanh-jet epilogue.
// BM=128, BN=128, BK=32, 256 thr, 8 warps in 2x4 grid, warp tile 64x32.
// Swizzled 64B rows (no padding), 3-stage cp.async, ONE sync per chunk,
// 2 CTAs/SM. MODE 1: jet(A@W1+b1) -> g_A2hi/lo ; MODE 2: -> g_S / g_Yb.
// ---------------------------------------------------------------------------
template<int MODE>
__global__ __launch_bounds__(256, 2)
void k_mma(const float* __restrict__ bias)
{
    const __half* __restrict__ Ahi = (MODE == 1) ? g_Ahi : g_A2hi;
    const __half* __restrict__ Alo = (MODE == 1) ? g_Alo : g_A2lo;
    const __half* __restrict__ Whi = (MODE == 1) ? g_W1hi : g_W2hi;
    const __half* __restrict__ Wlo = (MODE == 1) ? g_W1lo : g_W2lo;

    extern __shared__ char smem[];
    const uint32_t sbase = smem_u32(smem);

    const int tid  = threadIdx.x;
    const int lane = tid & 31;
    const int wid  = tid >> 5;        // 0..7
    const int wm   = wid >> 2;        // 0..1 : rows wm*64
    const int wn   = wid & 3;         // 0..3 : cols wn*32
    const int row0 = blockIdx.y * 128;
    const int col0 = blockIdx.x * 128;

    // ldmatrix lane decomposition. Row-tile bases are multiples of 16, so the
    // swizzle xor reduces to a per-lane constant: sx = (row_local>>1)&3.
    const int grp  = lane >> 3, idx = lane & 7;
    const int a_rl = (grp & 1) * 8 + idx;     // A row within 16
    const int a_cb = grp >> 1;                // A k-chunk half (16B units)
    const int a_sx = (a_rl >> 1) & 3;
    const int b_rl = (grp >> 1) * 8 + idx;    // B row within 16
    const int b_cb = grp & 1;
    const int b_sx = (b_rl >> 1) & 3;

    float acc[4][4][4];
    #pragma unroll
    for (int mt = 0; mt < 4; mt++)
        #pragma unroll
        for (int nt = 0; nt < 4; nt++)
            #pragma unroll
            for (int q = 0; q < 4; q++) acc[mt][nt][q] = 0.0f;

    // prefetch: 128 rows x 4 chunks (16B) per array; 2 chunks/thread/array
    const int fr = tid >> 1;            // 0..127
    const int jb = (tid & 1) * 2;       // chunk base: 0 or 2
    const int fsx = (fr >> 1) & 3;      // write-side swizzle
    auto prefetch = [&](int c) {
        uint32_t st = sbase + (uint32_t)(c % NSTAGE) * STAGE;
        #pragma unroll
        for (int j = 0; j < 2; j++) {
            int ch = jb + j;
            size_t ga = (size_t)(row0 + fr) * HID + c * 32 + ch * 8;
            size_t gb = (size_t)(col0 + fr) * HID + c * 32 + ch * 8;
            uint32_t o = (uint32_t)((fr << 6) + ((ch ^ fsx) << 4));
            cp16(st + SM_AHI + o, Ahi + ga);
            cp16(st + SM_ALO + o, Alo + ga);
            cp16(st + SM_BHI + o, Whi + gb);
            cp16(st + SM_BLO + o, Wlo + gb);
        }
        asm volatile("cp.async.commit_group;" ::: "memory");
    };

    prefetch(0);
    prefetch(1);

    for (int c = 0; c < NCH; c++) {
        if (c == NCH - 1) asm volatile("cp.async.wait_group 0;" ::: "memory");
        else              asm volatile("cp.async.wait_group 1;" ::: "memory");
        __syncthreads();
        // All warps finished reading stage (c-1)%3 before this barrier, so
        // stage (c+2)%3 == (c-1)%3 is safe to overwrite now.
        if (c + 2 < NCH) prefetch(c + 2);

        const uint32_t cur = sbase + (uint32_t)(c % NSTAGE) * STAGE;
        #pragma unroll
        for (int ks = 0; ks < 2; ks++) {
            uint32_t ahi[4][4], alo[4][4], bhi[2][4], blo[2][4];
            #pragma unroll
            for (int mt = 0; mt < 4; mt++) {
                uint32_t addr = cur
                    + (uint32_t)(((wm*64 + mt*16 + a_rl) << 6)
                    + ((((ks << 1) | a_cb) ^ a_sx) << 4));
                ldsm4(ahi[mt], addr + SM_AHI);
                ldsm4(alo[mt], addr + SM_ALO);
            }
            #pragma unroll
            for (int np = 0; np < 2; np++) {
                uint32_t addr = cur
                    + (uint32_t)(((wn*32 + np*16 + b_rl) << 6)
                    + ((((ks << 1) | b_cb) ^ b_sx) << 4));
                ldsm4(bhi[np], addr + SM_BHI);
                ldsm4(blo[np], addr + SM_BLO);
            }
            // hh pass, then lh, then hl (same-acc MMAs far apart; order preserved)
            #pragma unroll
            for (int mt = 0; mt < 4; mt++)
                #pragma unroll
                for (int nt = 0; nt < 4; nt++)
                    mma16816(acc[mt][nt], ahi[mt], &bhi[nt >> 1][(nt & 1) * 2]);
            #pragma unroll
            for (int mt = 0; mt < 4; mt++)
                #pragma unroll
                for (int nt = 0; nt < 4; nt++)
                    mma16816(acc[mt][nt], alo[mt], &bhi[nt >> 1][(nt & 1) * 2]);
            #pragma unroll
            for (int mt = 0; mt < 4; mt++)
                #pragma unroll
                for (int nt = 0; nt < 4; nt++)
                    mma16816(acc[mt][nt], ahi[mt], &blo[nt >> 1][(nt & 1) * 2]);
        }
    }

    // ---- epilogue: bias + tanh-jet ----
    float bb[4][2];
    #pragma unroll
    for (int nt = 0; nt < 4; nt++)
        #pragma unroll
        for (int j = 0; j < 2; j++)
            bb[nt][j] = __ldg(&bias[col0 + wn*32 + nt*8 + (lane & 3)*2 + j]);

    const int role = (lane >> 2) & 3;
    const int srcL = (lane & ~15) | (lane & 3);

    if (blockIdx.y < INT_TILES) {
        #pragma unroll
        for (int mt = 0; mt < 4; mt++)
            #pragma unroll
            for (int h = 0; h < 2; h++) {
                const int grow = row0 + wm*64 + mt*16 + (lane >> 2) + 8*h;
                #pragma unroll
                for (int nt = 0; nt < 4; nt++) {
                    float o[2];
                    #pragma unroll
                    for (int j = 0; j < 2; j++) {
                        float x  = acc[mt][nt][h*2 + j];
                        float v  = __shfl_sync(0xFFFFFFFFu, x, srcL);
                        float p0 = __shfl_sync(0xFFFFFFFFu, x, srcL + 4);
                        float p1 = __shfl_sync(0xFFFFFFFFu, x, srcL + 8);
                        float y  = tanhf(v + bb[nt][j]);
                        float s  = 1.0f - y*y;
                        float r;
                        if      (role == 0) r = y;
                        else if (role == 1) r = s * p0;
                        else if (role == 2) r = s * p1;
                        else                r = fmaf(s, x, -2.0f * y * s * (p0*p0 + p1*p1));
                        o[j] = r;
                    }
                    const int colb = col0 + wn*32 + nt*8 + (lane & 3)*2;
                    if (MODE == 1) {
                        uint32_t h0, l0, h1, l1;
                        hsplit(o[0], h0, l0);
                        hsplit(o[1], h1, l1);
                        size_t off = (size_t)grow * HID + colb;
                        *(uint32_t*)&g_A2hi[off] = h0 | (h1 << 16);
                        *(uint32_t*)&g_A2lo[off] = l0 | (l1 << 16);
                    } else if (role == 3) {
                        *(float2*)&g_S[(size_t)(grow >> 2) * HID + colb] = make_float2(o[0], o[1]);
                    }
                }
            }
    } else {
        #pragma unroll
        for (int mt = 0; mt < 4; mt++)
            #pragma unroll
            for (int h = 0; h < 2; h++) {
                const int grow = row0 + wm*64 + mt*16 + (lane >> 2) + 8*h;
                if (grow < M_ROWS) {
                    #pragma unroll
                    for (int nt = 0; nt < 4; nt++) {
                        float o0 = tanhf(acc[mt][nt][h*2 + 0] + bb[nt][0]);
                        float o1 = tanhf(acc[mt][nt][h*2 + 1] + bb[nt][1]);
                        const int colb = col0 + wn*32 + nt*8 + (lane & 3)*2;
                        if (MODE == 1) {
                            uint32_t h0, l0, h1, l1;
                            hsplit(o0, h0, l0);
                            hsplit(o1, h1, l1);
                            size_t off = (size_t)grow * HID + colb;
                            *(uint32_t*)&g_A2hi[off] = h0 | (h1 << 16);
                            *(uint32_t*)&g_A2lo[off] = l0 | (l1 << 16);
                        } else {
                            *(float2*)&g_Yb[(size_t)(grow - BROW) * HID + colb] = make_float2(o0, o1);
                        }
                    }
                }
            }
    }
}

// ---------------------------------------------------------------------------
// Final reductions (unchanged, proven).
// ---------------------------------------------------------------------------
__global__ void k_final_interior(const float* __restrict__ xi, const float* __restrict__ W3)
{
    int warp = threadIdx.x >> 5;
    int lane = threadIdx.x & 31;
    int p = blockIdx.x * 8 + warp;

    float val = 0.0f;
    if (p < N_INT) {
        const float* row = &g_S[(size_t)p * HID];
        float acc = 0.0f;
        #pragma unroll 4
        for (int j = lane; j < HID; j += 32) acc = fmaf(row[j], W3[j], acc);
        #pragma unroll
        for (int o = 16; o; o >>= 1) acc += __shfl_xor_sync(0xFFFFFFFFu, acc, o);
        if (lane == 0) {
            const float PI = 3.14159265358979323846f;
            float xx = xi[2*p], yy = xi[2*p+1];
            float sy2 = sinf(PI*yy*yy), cy2 = cosf(PI*yy*yy), sx = sinf(PI*xx);
            float f = -PI*PI*(1.0f + 4.0f*yy*yy)*sx*sy2 + 2.0f*PI*sx*cy2;
            float r = acc - f;
            val = r * r;
        }
    }
    __shared__ float sh[8];
    if (lane == 0) sh[warp] = val;
    __syncthreads();
    if (threadIdx.x == 0) {
        float s = 0.0f;
        #pragma unroll
        for (int i = 0; i < 8; i++) s += sh[i];
        g_partial_i[blockIdx.x] = s;
    }
}

__global__ void k_final_boundary(const float* __restrict__ W3, const float* __restrict__ b3)
{
    int warp = threadIdx.x >> 5;
    int lane = threadIdx.x & 31;
    int p = blockIdx.x * 8 + warp;

    float val = 0.0f;
    if (p < N_B) {
        const float* row = &g_Yb[(size_t)p * HID];
        float acc = 0.0f;
        #pragma unroll 4
        for (int j = lane; j < HID; j += 32) acc = fmaf(row[j], W3[j], acc);
        #pragma unroll
        for (int o = 16; o; o >>= 1) acc += __shfl_xor_sync(0xFFFFFFFFu, acc, o);
        if (lane == 0) {
            float u = acc + b3[0];
            val = u * u;
        }
    }
    __shared__ float sh[8];
    if (lane == 0) sh[warp] = val;
    __syncthreads();
    if (threadIdx.x == 0) {
        float s = 0.0f;
        #pragma unroll
        for (int i = 0; i < 8; i++) s += sh[i];
        g_partial_b[blockIdx.x] = s;
    }
}

__global__ void k_combine(float* __restrict__ out)
{
    __shared__ float sh[256];
    int t = threadIdx.x;

    float si = 0.0f;
    for (int i = t; i < 2500; i += 256) si += g_partial_i[i];
    sh[t] = si;
    __syncthreads();
    for (int o = 128; o; o >>= 1) { if (t < o) sh[t] += sh[t + o]; __syncthreads(); }
    float interior_sum = sh[0];
    __syncthreads();

    float sb = 0.0f;
    for (int i = t; i < 100; i += 256) sb += g_partial_b[i];
    sh[t] = sb;
    __syncthreads();
    for (int o = 128; o; o >>= 1) { if (t < o) sh[t] += sh[t + o]; __syncthreads(); }

    if (t == 0) {
        float interior_loss = interior_sum / (float)N_INT;
        float boundary_loss = sh[0] / (float)N_B;
        out[0] = ALPHA * interior_loss + boundary_loss;
        out[1] = interior_loss;
        out[2] = boundary_loss;
    }
}

// ---------------------------------------------------------------------------
extern "C" void kernel_launch(void* const* d_in, const int* in_sizes, int n_in,
                              void* d_out, int out_size)
{
    const float* xi = (const float*)d_in[0];
    const float* xb = (const float*)d_in[1];
    const float* W0 = (const float*)d_in[2];
    const float* b0 = (const float*)d_in[3];
    const float* W1 = (const float*)d_in[4];
    const float* b1 = (const float*)d_in[5];
    const float* W2 = (const float*)d_in[6];
    const float* b2 = (const float*)d_in[7];
    const float* W3 = (const float*)d_in[8];
    const float* b3 = (const float*)d_in[9];

    cudaFuncSetAttribute(k_mma<1>, cudaFuncAttributeMaxDynamicSharedMemorySize, SMEM_DYN);
    cudaFuncSetAttribute(k_mma<2>, cudaFuncAttributeMaxDynamicSharedMemorySize, SMEM_DYN);

    dim3 tgrid(16, 16), tblock(32, 32);
    dim3 mma_grid(4, M_TILES);

    k_layer0<<<N_INT + N_B, 256>>>(xi, xb, W0, b0);
    k_transpose<1><<<tgrid, tblock>>>(W1);
    k_transpose<2><<<tgrid, tblock>>>(W2);
    k_mma<1><<<mma_grid, 256, SMEM_DYN>>>(b1);
    k_mma<2><<<mma_grid, 256, SMEM_DYN>>>(b2);
    k_final_interior<<<(N_INT + 7) / 8, 256>>>(xi, W3);
    k_final_boundary<<<(N_B + 7) / 8, 256>>>(W3, b3);
    k_combine<<<1, 256>>>((float*)d_out);
}